// round 5
// baseline (speedup 1.0000x reference)
#include <cuda_runtime.h>
#include <math.h>
#include <stdint.h>

// Problem dims
#define BB 2
#define CC 384
#define HH 360
#define WW 720
#define LL 180
#define MM 181
#define NF 362                   // 2*MM (re/im planes interleaved by index k=2m+ri)
#define NRr 276480               // BB*CC*HH
#define BCn 768                  // BB*CC
#define BCL 138240               // BCn*LL
#define NTOT 199065600           // BB*CC*HH*WW

// Scratch (device globals; allocation-free)
__device__ float g_F[WW * NF];                       // forward DFT basis [w][k]
__device__ float g_Binv[NF * WW];                    // inverse basis [k][w], scale folded
__device__ float g_pctT[(size_t)MM * HH * LL];       // [m][h][l]
__device__ float g_ipctT[(size_t)MM * LL * HH];      // [m][l][h]
__device__ float g_xm[(size_t)NF * NRr];             // [k][row]  row=bc*360+h
__device__ float g_cf[(size_t)NF * BCL];             // [k][bc*180+l]
__device__ float g_xm2[(size_t)NF * NRr];            // [k][row]

// ---------------------------------------------------------------------------
// Basis construction: F[w][2m]=cos(2pi m w/720), F[w][2m+1]=-sin(...)
// Binv[2m][w]=(cm/720)cos, Binv[2m+1][w]=-(cm/720)sin, cm = (m==0?1:2)
__global__ void k_basis() {
    int idx = blockIdx.x * blockDim.x + threadIdx.x;
    if (idx >= MM * WW) return;
    int m = idx / WW, w = idx % WW;
    double t = 2.0 * (double)(m * w) / 720.0;  // in units of pi
    double s, c;
    sincospi(t, &s, &c);
    g_F[w * NF + 2 * m]     = (float)c;
    g_F[w * NF + 2 * m + 1] = (float)(-s);
    double sc = (m == 0 ? 1.0 : 2.0) / 720.0;
    g_Binv[(2 * m) * WW + w]     = (float)(sc * c);
    g_Binv[(2 * m + 1) * WW + w] = (float)(-sc * s);
}

// pctT[m][h][l] = pct[h][l][m]
__global__ void kT_pct(const float* __restrict__ pct) {
    size_t idx = (size_t)blockIdx.x * 256 + threadIdx.x;
    if (idx >= (size_t)MM * HH * LL) return;
    int l = (int)(idx % LL);
    size_t t = idx / LL;
    int h = (int)(t % HH);
    int m = (int)(t / HH);
    g_pctT[idx] = pct[((size_t)h * LL + l) * MM + m];
}

// ipctT[m][l][h] = ipct[h][l][m]
__global__ void kT_ipct(const float* __restrict__ ipct) {
    size_t idx = (size_t)blockIdx.x * 256 + threadIdx.x;
    if (idx >= (size_t)MM * LL * HH) return;
    int h = (int)(idx % HH);
    size_t t = idx / HH;
    int l = (int)(t % LL);
    int m = (int)(t / LL);
    g_ipctT[idx] = ipct[((size_t)h * LL + l) * MM + m];
}

// ---------------------------------------------------------------------------
// K1: xm[k][row] = sum_w X[row][w] * F[w][k]; 128x128 tile, BK=8, 8x8 micro
__global__ __launch_bounds__(256) void k1_dft(const float* __restrict__ X) {
    __shared__ float Xs[8][128];
    __shared__ float Fs[8][128];
    int row0 = blockIdx.x * 128;
    int n0 = blockIdx.y * 128;
    int tid = threadIdx.x;
    int tx = tid & 15;   // row direction (coalesced writes)
    int ty = tid >> 4;   // k (freq-plane) direction
    float acc[8][8];
#pragma unroll
    for (int j = 0; j < 8; j++)
#pragma unroll
        for (int i = 0; i < 8; i++) acc[j][i] = 0.f;

    for (int w0 = 0; w0 < WW; w0 += 8) {
        {
            int r = tid >> 1;
            int k4 = (tid & 1) * 4;
            float4 v = *(const float4*)(X + (size_t)(row0 + r) * WW + w0 + k4);
            Xs[k4 + 0][r] = v.x; Xs[k4 + 1][r] = v.y;
            Xs[k4 + 2][r] = v.z; Xs[k4 + 3][r] = v.w;
        }
        {
            int k = tid >> 5;
            int nb = (tid & 31) * 4;
            const float* Fr = g_F + (size_t)(w0 + k) * NF;
#pragma unroll
            for (int j = 0; j < 4; j++) {
                int n = n0 + nb + j;
                Fs[k][nb + j] = (n < NF) ? Fr[n] : 0.f;
            }
        }
        __syncthreads();
#pragma unroll
        for (int k = 0; k < 8; k++) {
            float a[8], b[8];
#pragma unroll
            for (int i = 0; i < 8; i++) a[i] = Xs[k][tx + 16 * i];
#pragma unroll
            for (int j = 0; j < 8; j++) b[j] = Fs[k][ty + 16 * j];
#pragma unroll
            for (int j = 0; j < 8; j++)
#pragma unroll
                for (int i = 0; i < 8; i++) acc[j][i] += a[i] * b[j];
        }
        __syncthreads();
    }
#pragma unroll
    for (int j = 0; j < 8; j++) {
        int n = n0 + ty + 16 * j;
        if (n >= NF) continue;
        float* o = g_xm + (size_t)n * NRr + row0;
#pragma unroll
        for (int i = 0; i < 8; i++) o[tx + 16 * i] = acc[j][i];
    }
}

// ---------------------------------------------------------------------------
// K2: per m: C[bc][l] = sum_h xm[2m|2m+1][bc*360+h] * pctT[m][h][l],
//     then complex weight multiply. 64x64 tile, BK=8, 4x4x2 micro.
__global__ __launch_bounds__(256) void k2_pct(const float* __restrict__ weight) {
    int m = blockIdx.z;
    int bc0 = blockIdx.x * 64;
    int l0 = blockIdx.y * 64;
    __shared__ float Ar[8][64], Ai[8][64], Ps[8][64];
    int tid = threadIdx.x;
    int tx = tid & 15;   // l
    int ty = tid >> 4;   // bc
    float accR[4][4], accI[4][4];
#pragma unroll
    for (int i = 0; i < 4; i++)
#pragma unroll
        for (int j = 0; j < 4; j++) { accR[i][j] = 0.f; accI[i][j] = 0.f; }

    const float* xr = g_xm + (size_t)(2 * m) * NRr;
    const float* xi = g_xm + (size_t)(2 * m + 1) * NRr;

    for (int h0 = 0; h0 < HH; h0 += 8) {
        {
            int r = tid >> 2;
            int k2 = (tid & 3) * 2;
            size_t base = (size_t)(bc0 + r) * HH + h0 + k2;
            float2 vr = *(const float2*)(xr + base);
            Ar[k2][r] = vr.x; Ar[k2 + 1][r] = vr.y;
            float2 vi = *(const float2*)(xi + base);
            Ai[k2][r] = vi.x; Ai[k2 + 1][r] = vi.y;
        }
        {
            int k = tid >> 5;
            int c2 = (tid & 31) * 2;
            const float* Pm = g_pctT + ((size_t)m * HH + h0 + k) * LL;
#pragma unroll
            for (int j = 0; j < 2; j++) {
                int l = l0 + c2 + j;
                Ps[k][c2 + j] = (l < LL) ? Pm[l] : 0.f;
            }
        }
        __syncthreads();
#pragma unroll
        for (int k = 0; k < 8; k++) {
            float ar[4], ai[4], p[4];
#pragma unroll
            for (int i = 0; i < 4; i++) { ar[i] = Ar[k][ty + 16 * i]; ai[i] = Ai[k][ty + 16 * i]; }
#pragma unroll
            for (int j = 0; j < 4; j++) p[j] = Ps[k][tx + 16 * j];
#pragma unroll
            for (int i = 0; i < 4; i++)
#pragma unroll
                for (int j = 0; j < 4; j++) {
                    accR[i][j] += ar[i] * p[j];
                    accI[i][j] += ai[i] * p[j];
                }
        }
        __syncthreads();
    }
    float* cr = g_cf + (size_t)(2 * m) * BCL;
    float* ci = g_cf + (size_t)(2 * m + 1) * BCL;
#pragma unroll
    for (int i = 0; i < 4; i++) {
        int bc = bc0 + ty + 16 * i;
        int c = bc % CC;
#pragma unroll
        for (int j = 0; j < 4; j++) {
            int l = l0 + tx + 16 * j;
            if (l >= LL) continue;
            float2 wv = *(const float2*)(weight + (((size_t)c * LL + l) * MM + m) * 2);
            size_t o = (size_t)bc * LL + l;
            cr[o] = accR[i][j] * wv.x - accI[i][j] * wv.y;
            ci[o] = accR[i][j] * wv.y + accI[i][j] * wv.x;
        }
    }
}

// ---------------------------------------------------------------------------
// K3: per m: xm2[2m|2m+1][bc*360+h] = sum_l cf[...][bc*180+l] * ipctT[m][l][h]
__global__ __launch_bounds__(256) void k3_ipct() {
    int m = blockIdx.z;
    int bc0 = blockIdx.x * 64;
    int h0 = blockIdx.y * 64;
    __shared__ float Ar[8][64], Ai[8][64], Qs[8][64];
    int tid = threadIdx.x;
    int tx = tid & 15;   // h
    int ty = tid >> 4;   // bc
    float accR[4][4], accI[4][4];
#pragma unroll
    for (int i = 0; i < 4; i++)
#pragma unroll
        for (int j = 0; j < 4; j++) { accR[i][j] = 0.f; accI[i][j] = 0.f; }

    const float* cr = g_cf + (size_t)(2 * m) * BCL;
    const float* ci = g_cf + (size_t)(2 * m + 1) * BCL;

    for (int l0 = 0; l0 < LL; l0 += 8) {
        {
            int r = tid >> 2;
            int k2 = (tid & 3) * 2;
            int l = l0 + k2;
            size_t base = (size_t)(bc0 + r) * LL + l;
            Ar[k2][r]     = (l < LL)     ? cr[base]     : 0.f;
            Ar[k2 + 1][r] = (l + 1 < LL) ? cr[base + 1] : 0.f;
            Ai[k2][r]     = (l < LL)     ? ci[base]     : 0.f;
            Ai[k2 + 1][r] = (l + 1 < LL) ? ci[base + 1] : 0.f;
        }
        {
            int k = tid >> 5;
            int c2 = (tid & 31) * 2;
            int l = l0 + k;
            const float* Qm = g_ipctT + ((size_t)m * LL + l) * HH;
#pragma unroll
            for (int j = 0; j < 2; j++) {
                int h = h0 + c2 + j;
                Qs[k][c2 + j] = (l < LL && h < HH) ? Qm[h] : 0.f;
            }
        }
        __syncthreads();
#pragma unroll
        for (int k = 0; k < 8; k++) {
            float ar[4], ai[4], q[4];
#pragma unroll
            for (int i = 0; i < 4; i++) { ar[i] = Ar[k][ty + 16 * i]; ai[i] = Ai[k][ty + 16 * i]; }
#pragma unroll
            for (int j = 0; j < 4; j++) q[j] = Qs[k][tx + 16 * j];
#pragma unroll
            for (int i = 0; i < 4; i++)
#pragma unroll
                for (int j = 0; j < 4; j++) {
                    accR[i][j] += ar[i] * q[j];
                    accI[i][j] += ai[i] * q[j];
                }
        }
        __syncthreads();
    }
    float* orp = g_xm2 + (size_t)(2 * m) * NRr;
    float* oip = g_xm2 + (size_t)(2 * m + 1) * NRr;
#pragma unroll
    for (int i = 0; i < 4; i++) {
        int bc = bc0 + ty + 16 * i;
#pragma unroll
        for (int j = 0; j < 4; j++) {
            int h = h0 + tx + 16 * j;
            if (h >= HH) continue;
            size_t o = (size_t)bc * HH + h;
            orp[o] = accR[i][j];
            oip[o] = accI[i][j];
        }
    }
}

// ---------------------------------------------------------------------------
// K4: out[row][w] = sum_k xm2[k][row] * Binv[k][w]; 128x128 tile, BK=8
__global__ __launch_bounds__(256) void k4_idft(float* __restrict__ out) {
    __shared__ float As[8][128];
    __shared__ float Bs[8][128];
    int row0 = blockIdx.x * 128;
    int w0 = blockIdx.y * 128;
    int tid = threadIdx.x;
    int tx = tid & 15;   // w (coalesced writes)
    int ty = tid >> 4;   // row
    float acc[8][8];
#pragma unroll
    for (int i = 0; i < 8; i++)
#pragma unroll
        for (int j = 0; j < 8; j++) acc[i][j] = 0.f;

    for (int k0 = 0; k0 < 368; k0 += 8) {
        {
            int k = tid >> 5;
            int r4 = (tid & 31) * 4;
            if (k0 + k < NF) {
                float4 v = *(const float4*)(g_xm2 + (size_t)(k0 + k) * NRr + row0 + r4);
                As[k][r4 + 0] = v.x; As[k][r4 + 1] = v.y;
                As[k][r4 + 2] = v.z; As[k][r4 + 3] = v.w;
            } else {
                As[k][r4 + 0] = 0.f; As[k][r4 + 1] = 0.f;
                As[k][r4 + 2] = 0.f; As[k][r4 + 3] = 0.f;
            }
        }
        {
            int k = tid >> 5;
            int c4 = (tid & 31) * 4;
            const float* Br = g_Binv + (size_t)(k0 + k) * WW;
#pragma unroll
            for (int j = 0; j < 4; j++) {
                int w = w0 + c4 + j;
                Bs[k][c4 + j] = (k0 + k < NF && w < WW) ? Br[w] : 0.f;
            }
        }
        __syncthreads();
#pragma unroll
        for (int k = 0; k < 8; k++) {
            float a[8], b[8];
#pragma unroll
            for (int i = 0; i < 8; i++) a[i] = As[k][ty + 16 * i];
#pragma unroll
            for (int j = 0; j < 8; j++) b[j] = Bs[k][tx + 16 * j];
#pragma unroll
            for (int i = 0; i < 8; i++)
#pragma unroll
                for (int j = 0; j < 8; j++) acc[i][j] += a[i] * b[j];
        }
        __syncthreads();
    }
#pragma unroll
    for (int i = 0; i < 8; i++) {
        int row = row0 + ty + 16 * i;
        float* o = out + (size_t)row * WW;
#pragma unroll
        for (int j = 0; j < 8; j++) {
            int w = w0 + tx + 16 * j;
            if (w < WW) o[w] = acc[i][j];
        }
    }
}

// ---------------------------------------------------------------------------
extern "C" void kernel_launch(void* const* d_in, const int* in_sizes, int n_in,
                              void* d_out, int out_size) {
    const float* x      = (const float*)d_in[0];
    const float* weight = (const float*)d_in[1];
    const float* pct    = (const float*)d_in[2];
    const float* ipct   = (const float*)d_in[3];
    float* out = (float*)d_out;

    k_basis<<<(MM * WW + 255) / 256, 256>>>();
    {
        size_t n = (size_t)MM * HH * LL;
        kT_pct<<<(unsigned)((n + 255) / 256), 256>>>(pct);
        kT_ipct<<<(unsigned)((n + 255) / 256), 256>>>(ipct);
    }
    k1_dft<<<dim3(NRr / 128, 3), 256>>>(x);
    k2_pct<<<dim3(12, 3, MM), 256>>>(weight);
    k3_ipct<<<dim3(12, 6, MM), 256>>>();
    k4_idft<<<dim3(NRr / 128, 6), 256>>>(out);

    if ((long long)out_size >= 2LL * NTOT) {
        cudaMemcpyAsync(out + NTOT, x, (size_t)NTOT * sizeof(float),
                        cudaMemcpyDeviceToDevice);
    }
}

// round 7
// speedup vs baseline: 1.6912x; 1.6912x over previous
#include <cuda_runtime.h>
#include <math.h>
#include <stdint.h>

// Problem dims
#define BB 2
#define CC 384
#define HH 360
#define WW 720
#define LL 180
#define MM 181
#define NF 362                   // 2*MM re/im planes
#define NRr 276480               // BB*CC*HH
#define BCL 138240               // BB*CC*LL
#define NTOT 199065600           // BB*CC*HH*WW

#define KE 368                   // padded fold length (361/359 -> 368)
#define NP1 192                  // padded m-dim for forward GEMM (181 -> 192)
#define NP4 384                  // padded w-dim for inverse GEMM (361/359 -> 384)

// Scratch (device globals; allocation-free; zero-initialized at load)
__device__ float g_e[(size_t)NRr * KE];          // even fold [row][k]
__device__ float g_o[(size_t)NRr * KE];          // odd fold  [row][k]
__device__ float g_Fc[KE * NP1];                 // fwd cos basis [k][m]
__device__ float g_Fs[KE * NP1];                 // fwd -sin basis [k][m]
__device__ float g_Ic[NP1 * NP4];                // inv cos basis [m][w]
__device__ float g_Is[NP1 * NP4];                // inv sin basis [m][w]
__device__ float g_pctT[(size_t)MM * HH * LL];   // [m][h][l]
__device__ float g_ipctT[(size_t)MM * LL * HH];  // [m][l][h]
__device__ float g_xm[(size_t)(2 * NP1) * NRr];  // [2m+ri][row], padded planes
__device__ float g_cf[(size_t)NF * BCL];         // [2m+ri][bc*180+l]
__device__ float g_xm2[(size_t)(2 * NP1) * NRr]; // [2m+ri][row], padded planes
__device__ float g_C[(size_t)NRr * NP4];         // cos half-synthesis [row][w]
__device__ float g_S[(size_t)NRr * NP4];         // sin half-synthesis [row][w-1]

// ---------------------------------------------------------------------------
// Forward bases: Fc[k][n]=cos(2pi n k/720) (k=w, 0..360)
//                Fs[k][n]=-sin(2pi n (k+1)/720) (k+1=w, 1..359)
__global__ void kb_f() {
    int idx = blockIdx.x * 256 + threadIdx.x;
    if (idx >= KE * NP1) return;
    int k = idx / NP1, n = idx % NP1;
    float fc = 0.f, fs = 0.f;
    if (n <= 180) {
        double s, c;
        if (k <= 360) { sincospi((double)(n * k) / 360.0, &s, &c); fc = (float)c; }
        if (k <= 358) { sincospi((double)(n * (k + 1)) / 360.0, &s, &c); fs = (float)(-s); }
    }
    g_Fc[idx] = fc;
    g_Fs[idx] = fs;
}

// Inverse bases: Ic[m][j]=(c_m/720)cos(2pi m j/720) (j=w, 0..360)
//                Is[m][j]=(c_m/720)sin(2pi m (j+1)/720) (j+1=w, 1..359)
__global__ void kb_i() {
    int idx = blockIdx.x * 256 + threadIdx.x;
    if (idx >= NP1 * NP4) return;
    int m = idx / NP4, j = idx % NP4;
    float ic = 0.f, is = 0.f;
    if (m <= 180) {
        double sc = (m == 0 ? 1.0 : 2.0) / 720.0;
        double s, c;
        if (j <= 360) { sincospi((double)(m * j) / 360.0, &s, &c); ic = (float)(sc * c); }
        if (j <= 358) { sincospi((double)(m * (j + 1)) / 360.0, &s, &c); is = (float)(sc * s); }
    }
    g_Ic[idx] = ic;
    g_Is[idx] = is;
}

// pctT[m][h][l] = pct[h][l][m]
__global__ void kT_pct(const float* __restrict__ pct) {
    size_t idx = (size_t)blockIdx.x * 256 + threadIdx.x;
    if (idx >= (size_t)MM * HH * LL) return;
    int l = (int)(idx % LL);
    size_t t = idx / LL;
    int h = (int)(t % HH);
    int m = (int)(t / HH);
    g_pctT[idx] = pct[((size_t)h * LL + l) * MM + m];
}

// ipctT[m][l][h] = ipct[h][l][m]
__global__ void kT_ipct(const float* __restrict__ ipct) {
    size_t idx = (size_t)blockIdx.x * 256 + threadIdx.x;
    if (idx >= (size_t)MM * LL * HH) return;
    int h = (int)(idx % HH);
    size_t t = idx / HH;
    int l = (int)(t % LL);
    int m = (int)(t / LL);
    g_ipctT[idx] = ipct[((size_t)h * LL + l) * MM + m];
}

// ---------------------------------------------------------------------------
// Fold: E[row][w]=x[w]+x[720-w] (w=1..359), E[0]=x[0], E[360]=x[360]
//       O[row][w-1]=x[w]-x[720-w] (w=1..359). Pad cols stay zero (zero-init,
//       and the basis rows there are zero anyway).
__global__ void k_fold(const float* __restrict__ x) {
    unsigned idx = blockIdx.x * 256u + threadIdx.x;
    if (idx >= (unsigned)(NRr * 360)) return;
    int row = idx / 360;
    int w = idx - row * 360;
    const float* xr = x + (size_t)row * WW;
    float* er = g_e + (size_t)row * KE;
    float* orow = g_o + (size_t)row * KE;
    if (w == 0) {
        er[0] = xr[0];
        er[360] = xr[360];
    } else {
        float a = xr[w], b = xr[WW - w];
        er[w] = a + b;
        orow[w - 1] = a - b;
    }
}

// ---------------------------------------------------------------------------
// Forward GEMM: out[n-plane][row] = sum_k A[row][k] * Bb[k][n]
// A row-major [NRr][KE], Bb [KE][NP1]; out planes stride 2*NRr (re/im interleave).
// Tile: 128 rows x 64 n, BK=16, 256 threads, micro 4(row,f4) x 8(n).
__global__ __launch_bounds__(256) void g1(const float* __restrict__ A,
                                          const float* __restrict__ Bb,
                                          float* __restrict__ outBase) {
    __shared__ float As[16][132];
    __shared__ float Bs[16][68];
    int row0 = blockIdx.x * 128;
    int n0 = blockIdx.y * 64;
    int tid = threadIdx.x;
    int tx = tid & 31;   // row micro (x4)
    int ty = tid >> 5;   // n micro (x8)
    float acc[8][4];
#pragma unroll
    for (int j = 0; j < 8; j++)
#pragma unroll
        for (int i = 0; i < 4; i++) acc[j][i] = 0.f;

    int lr = tid >> 1;
    int lkq = (tid & 1) * 8;
    int lkb = tid >> 4;
    int lnv = (tid & 15) * 4;
    const float* arow = A + (size_t)(row0 + lr) * KE + lkq;

    for (int k0 = 0; k0 < KE; k0 += 16) {
        {
            float4 v0 = *(const float4*)(arow + k0);
            float4 v1 = *(const float4*)(arow + k0 + 4);
            As[lkq + 0][lr] = v0.x; As[lkq + 1][lr] = v0.y;
            As[lkq + 2][lr] = v0.z; As[lkq + 3][lr] = v0.w;
            As[lkq + 4][lr] = v1.x; As[lkq + 5][lr] = v1.y;
            As[lkq + 6][lr] = v1.z; As[lkq + 7][lr] = v1.w;
        }
        *(float4*)&Bs[lkb][lnv] =
            *(const float4*)(Bb + (size_t)(k0 + lkb) * NP1 + n0 + lnv);
        __syncthreads();
#pragma unroll
        for (int kk = 0; kk < 16; kk++) {
            float4 a4 = *(const float4*)&As[kk][tx * 4];
            float4 b0 = *(const float4*)&Bs[kk][ty * 8];
            float4 b1 = *(const float4*)&Bs[kk][ty * 8 + 4];
            float av[4] = {a4.x, a4.y, a4.z, a4.w};
            float bv[8] = {b0.x, b0.y, b0.z, b0.w, b1.x, b1.y, b1.z, b1.w};
#pragma unroll
            for (int j = 0; j < 8; j++)
#pragma unroll
                for (int i = 0; i < 4; i++) acc[j][i] += bv[j] * av[i];
        }
        __syncthreads();
    }
#pragma unroll
    for (int j = 0; j < 8; j++) {
        size_t n = n0 + ty * 8 + j;
        float4 st = make_float4(acc[j][0], acc[j][1], acc[j][2], acc[j][3]);
        *(float4*)(outBase + n * (size_t)(2 * NRr) + row0 + tx * 4) = st;
    }
}

// ---------------------------------------------------------------------------
// K2: per m: C[bc][l] = sum_h xm[2m|2m+1][bc*360+h] * pctT[m][h][l], * complex W
__global__ __launch_bounds__(256) void k2_pct(const float* __restrict__ weight) {
    int m = blockIdx.z;
    int bc0 = blockIdx.x * 64;
    int l0 = blockIdx.y * 64;
    __shared__ float Ar[8][64], Ai[8][64], Ps[8][64];
    int tid = threadIdx.x;
    int tx = tid & 15;   // l micro (x4)
    int ty = tid >> 4;   // bc micro (x4)
    float accR[4][4], accI[4][4];
#pragma unroll
    for (int i = 0; i < 4; i++)
#pragma unroll
        for (int j = 0; j < 4; j++) { accR[i][j] = 0.f; accI[i][j] = 0.f; }

    const float* xr = g_xm + (size_t)(2 * m) * NRr;
    const float* xi = xr + NRr;

    for (int h0 = 0; h0 < HH; h0 += 8) {
        {
            int r = tid >> 2;
            int k2 = (tid & 3) * 2;
            size_t base = (size_t)(bc0 + r) * HH + h0 + k2;
            float2 vr = *(const float2*)(xr + base);
            Ar[k2][r] = vr.x; Ar[k2 + 1][r] = vr.y;
            float2 vi = *(const float2*)(xi + base);
            Ai[k2][r] = vi.x; Ai[k2 + 1][r] = vi.y;
        }
        {
            int k = tid >> 5;
            int c2 = (tid & 31) * 2;
            const float* Pm = g_pctT + ((size_t)m * HH + h0 + k) * LL;
#pragma unroll
            for (int j = 0; j < 2; j++) {
                int l = l0 + c2 + j;
                Ps[k][c2 + j] = (l < LL) ? Pm[l] : 0.f;
            }
        }
        __syncthreads();
#pragma unroll
        for (int k = 0; k < 8; k++) {
            float4 ar4 = *(const float4*)&Ar[k][ty * 4];
            float4 ai4 = *(const float4*)&Ai[k][ty * 4];
            float4 p4 = *(const float4*)&Ps[k][tx * 4];
            float arv[4] = {ar4.x, ar4.y, ar4.z, ar4.w};
            float aiv[4] = {ai4.x, ai4.y, ai4.z, ai4.w};
            float pv[4] = {p4.x, p4.y, p4.z, p4.w};
#pragma unroll
            for (int i = 0; i < 4; i++)
#pragma unroll
                for (int j = 0; j < 4; j++) {
                    accR[i][j] += arv[i] * pv[j];
                    accI[i][j] += aiv[i] * pv[j];
                }
        }
        __syncthreads();
    }
    float* cr = g_cf + (size_t)(2 * m) * BCL;
    float* ci = cr + BCL;
#pragma unroll
    for (int i = 0; i < 4; i++) {
        int bc = bc0 + ty * 4 + i;
        int c = bc % CC;
#pragma unroll
        for (int j = 0; j < 4; j++) {
            int l = l0 + tx * 4 + j;
            if (l >= LL) continue;
            float2 wv = *(const float2*)(weight + (((size_t)c * LL + l) * MM + m) * 2);
            size_t o = (size_t)bc * LL + l;
            cr[o] = accR[i][j] * wv.x - accI[i][j] * wv.y;
            ci[o] = accR[i][j] * wv.y + accI[i][j] * wv.x;
        }
    }
}

// ---------------------------------------------------------------------------
// K3: per m: xm2[2m|2m+1][bc*360+h] = sum_l cf[...][bc*180+l] * ipctT[m][l][h]
__global__ __launch_bounds__(256) void k3_ipct() {
    int m = blockIdx.z;
    int bc0 = blockIdx.x * 64;
    int h0 = blockIdx.y * 64;
    __shared__ float Ar[8][64], Ai[8][64], Qs[8][64];
    int tid = threadIdx.x;
    int tx = tid & 15;   // h micro (x4)
    int ty = tid >> 4;   // bc micro (x4)
    float accR[4][4], accI[4][4];
#pragma unroll
    for (int i = 0; i < 4; i++)
#pragma unroll
        for (int j = 0; j < 4; j++) { accR[i][j] = 0.f; accI[i][j] = 0.f; }

    const float* cr = g_cf + (size_t)(2 * m) * BCL;
    const float* ci = cr + BCL;

    for (int l0 = 0; l0 < LL; l0 += 8) {
        {
            int r = tid >> 2;
            int k2 = (tid & 3) * 2;
            int l = l0 + k2;
            size_t base = (size_t)(bc0 + r) * LL + l;
            Ar[k2][r]     = (l < LL)     ? cr[base]     : 0.f;
            Ar[k2 + 1][r] = (l + 1 < LL) ? cr[base + 1] : 0.f;
            Ai[k2][r]     = (l < LL)     ? ci[base]     : 0.f;
            Ai[k2 + 1][r] = (l + 1 < LL) ? ci[base + 1] : 0.f;
        }
        {
            int k = tid >> 5;
            int c2 = (tid & 31) * 2;
            int l = l0 + k;
            const float* Qm = g_ipctT + ((size_t)m * LL + l) * HH;
#pragma unroll
            for (int j = 0; j < 2; j++) {
                int h = h0 + c2 + j;
                Qs[k][c2 + j] = (l < LL && h < HH) ? Qm[h] : 0.f;
            }
        }
        __syncthreads();
#pragma unroll
        for (int k = 0; k < 8; k++) {
            float4 ar4 = *(const float4*)&Ar[k][ty * 4];
            float4 ai4 = *(const float4*)&Ai[k][ty * 4];
            float4 q4 = *(const float4*)&Qs[k][tx * 4];
            float arv[4] = {ar4.x, ar4.y, ar4.z, ar4.w};
            float aiv[4] = {ai4.x, ai4.y, ai4.z, ai4.w};
            float qv[4] = {q4.x, q4.y, q4.z, q4.w};
#pragma unroll
            for (int i = 0; i < 4; i++)
#pragma unroll
                for (int j = 0; j < 4; j++) {
                    accR[i][j] += arv[i] * qv[j];
                    accI[i][j] += aiv[i] * qv[j];
                }
        }
        __syncthreads();
    }
    float* orp = g_xm2 + (size_t)(2 * m) * NRr;
    float* oip = orp + NRr;
#pragma unroll
    for (int i = 0; i < 4; i++) {
        int bc = bc0 + ty * 4 + i;
#pragma unroll
        for (int j = 0; j < 4; j++) {
            int h = h0 + tx * 4 + j;
            if (h >= HH) continue;
            size_t o = (size_t)bc * HH + h;
            orp[o] = accR[i][j];
            oip[o] = accI[i][j];
        }
    }
}

// ---------------------------------------------------------------------------
// Inverse GEMM: Cout[row][w] = sum_m Aplane[m][row] * Bb[m][w]
// A planes (k-major, stride 2*NRr), Bb [NP1][NP4]; Cout row-major [NRr][NP4].
// Tile: 64 rows x 128 w, BK=16, 256 threads, micro 8(row) x 4(w,f4).
__global__ __launch_bounds__(256) void g4(const float* __restrict__ Abase,
                                          const float* __restrict__ Bb,
                                          float* __restrict__ Cout) {
    __shared__ float As[16][68];
    __shared__ float Bs[16][132];
    int row0 = blockIdx.x * 64;
    int w0 = blockIdx.y * 128;
    int tid = threadIdx.x;
    int tx = tid & 31;   // w micro (x4)
    int ty = tid >> 5;   // row micro (x8)
    float acc[8][4];
#pragma unroll
    for (int i = 0; i < 8; i++)
#pragma unroll
        for (int j = 0; j < 4; j++) acc[i][j] = 0.f;

    int lkb = tid >> 4;
    int lrv = (tid & 15) * 4;
    int lwv = (tid & 15) * 8;

    for (int k0 = 0; k0 < NP1; k0 += 16) {
        *(float4*)&As[lkb][lrv] =
            *(const float4*)(Abase + (size_t)(k0 + lkb) * (2 * NRr) + row0 + lrv);
        const float* brow = Bb + (size_t)(k0 + lkb) * NP4 + w0 + lwv;
        *(float4*)&Bs[lkb][lwv] = *(const float4*)(brow);
        *(float4*)&Bs[lkb][lwv + 4] = *(const float4*)(brow + 4);
        __syncthreads();
#pragma unroll
        for (int kk = 0; kk < 16; kk++) {
            float4 b4 = *(const float4*)&Bs[kk][tx * 4];
            float4 a0 = *(const float4*)&As[kk][ty * 8];
            float4 a1 = *(const float4*)&As[kk][ty * 8 + 4];
            float bv[4] = {b4.x, b4.y, b4.z, b4.w};
            float av[8] = {a0.x, a0.y, a0.z, a0.w, a1.x, a1.y, a1.z, a1.w};
#pragma unroll
            for (int i = 0; i < 8; i++)
#pragma unroll
                for (int j = 0; j < 4; j++) acc[i][j] += av[i] * bv[j];
        }
        __syncthreads();
    }
#pragma unroll
    for (int i = 0; i < 8; i++) {
        int row = row0 + ty * 8 + i;
        float4 st = make_float4(acc[i][0], acc[i][1], acc[i][2], acc[i][3]);
        *(float4*)(Cout + (size_t)row * NP4 + w0 + tx * 4) = st;
    }
}

// ---------------------------------------------------------------------------
// Combine: out[row][w] = C[w]-S[w], out[row][720-w] = C[w]+S[w] (w=1..359)
//          out[row][0] = C[0], out[row][360] = C[360]
__global__ void k_combine(float* __restrict__ out) {
    unsigned idx = blockIdx.x * 256u + threadIdx.x;
    if (idx >= (unsigned)(NRr * 361)) return;
    int row = idx / 361;
    int w = idx - row * 361;
    float c = g_C[(size_t)row * NP4 + w];
    float* o = out + (size_t)row * WW;
    if (w == 0) {
        o[0] = c;
    } else if (w == 360) {
        o[360] = c;
    } else {
        float s = g_S[(size_t)row * NP4 + (w - 1)];
        o[w] = c - s;
        o[WW - w] = c + s;
    }
}

// ---------------------------------------------------------------------------
extern "C" void kernel_launch(void* const* d_in, const int* in_sizes, int n_in,
                              void* d_out, int out_size) {
    const float* x      = (const float*)d_in[0];
    const float* weight = (const float*)d_in[1];
    const float* pct    = (const float*)d_in[2];
    const float* ipct   = (const float*)d_in[3];
    float* out = (float*)d_out;

    // Resolve REAL device addresses of the __device__ globals for use as
    // kernel arguments. (Taking &g_e in host code yields the host shadow —
    // that was the R6 bug.) cudaGetSymbolAddress is a pure lookup: legal
    // during graph capture, no allocation.
    float *p_e, *p_o, *p_Fc, *p_Fs, *p_Ic, *p_Is, *p_xm, *p_xm2, *p_C, *p_S;
    cudaGetSymbolAddress((void**)&p_e,   g_e);
    cudaGetSymbolAddress((void**)&p_o,   g_o);
    cudaGetSymbolAddress((void**)&p_Fc,  g_Fc);
    cudaGetSymbolAddress((void**)&p_Fs,  g_Fs);
    cudaGetSymbolAddress((void**)&p_Ic,  g_Ic);
    cudaGetSymbolAddress((void**)&p_Is,  g_Is);
    cudaGetSymbolAddress((void**)&p_xm,  g_xm);
    cudaGetSymbolAddress((void**)&p_xm2, g_xm2);
    cudaGetSymbolAddress((void**)&p_C,   g_C);
    cudaGetSymbolAddress((void**)&p_S,   g_S);

    kb_f<<<(KE * NP1 + 255) / 256, 256>>>();
    kb_i<<<(NP1 * NP4 + 255) / 256, 256>>>();
    {
        size_t n = (size_t)MM * HH * LL;
        kT_pct<<<(unsigned)((n + 255) / 256), 256>>>(pct);
        kT_ipct<<<(unsigned)((n + 255) / 256), 256>>>(ipct);
    }
    k_fold<<<(NRr * 360 + 255) / 256, 256>>>(x);

    // Forward transform: Re plane from E x cos, Im plane from O x (-sin)
    g1<<<dim3(NRr / 128, NP1 / 64), 256>>>(p_e, p_Fc, p_xm);
    g1<<<dim3(NRr / 128, NP1 / 64), 256>>>(p_o, p_Fs, p_xm + NRr);

    k2_pct<<<dim3(12, 3, MM), 256>>>(weight);
    k3_ipct<<<dim3(12, 6, MM), 256>>>();

    // Inverse transform half-syntheses
    g4<<<dim3(NRr / 64, NP4 / 128), 256>>>(p_xm2, p_Ic, p_C);
    g4<<<dim3(NRr / 64, NP4 / 128), 256>>>(p_xm2 + NRr, p_Is, p_S);

    k_combine<<<(NRr * 361 + 255) / 256, 256>>>(out);

    if ((long long)out_size >= 2LL * NTOT) {
        cudaMemcpyAsync(out + NTOT, x, (size_t)NTOT * sizeof(float),
                        cudaMemcpyDeviceToDevice);
    }
}